// round 1
// baseline (speedup 1.0000x reference)
#include <cuda_runtime.h>

#define NN 50000
#define IN_FT 256
#define OUT_FT 64
#define NE 800000

// Scratch for fc(seq): [N, 64] fp32 = 12.8 MB. Device global (no allocation allowed).
__device__ float g_fts[NN * OUT_FT];

// ---------------------------------------------------------------------------
// GEMM: fts[n][o] = sum_k seq[n][k] * W[o][k]
// Tile: BM=64 rows, BN=64 cols (all), BK=32. 256 threads, each computes 4x4.
// ---------------------------------------------------------------------------
__global__ __launch_bounds__(256) void gemm_kernel(
    const float* __restrict__ seq, const float* __restrict__ W,
    float* __restrict__ fts)
{
    __shared__ float sA[64 * 32];   // [row][k] row-major, 8 KB
    __shared__ float sB[32 * 64];   // [k][col], 8 KB

    const int t  = threadIdx.x;
    const int tx = t & 15;          // col group: cols tx*4 .. tx*4+3
    const int ty = t >> 4;          // row group: rows ty*4 .. ty*4+3
    const int row0 = blockIdx.x * 64;

    float acc[4][4];
#pragma unroll
    for (int r = 0; r < 4; r++)
#pragma unroll
        for (int c = 0; c < 4; c++) acc[r][c] = 0.0f;

    for (int kt = 0; kt < IN_FT; kt += 32) {
        // Load seq tile: 64 rows x 32 k = 512 float4, 2 per thread.
#pragma unroll
        for (int i = 0; i < 2; i++) {
            int idx = t + i * 256;          // 0..511
            int r   = idx >> 3;             // row 0..63
            int kq  = idx & 7;              // float4 slot in k
            float4 v = make_float4(0.f, 0.f, 0.f, 0.f);
            if (row0 + r < NN)
                v = *(const float4*)&seq[(size_t)(row0 + r) * IN_FT + kt + kq * 4];
            *(float4*)&sA[r * 32 + kq * 4] = v;
        }
        // Load W tile transposed: W[o][k] -> sB[k][o]
#pragma unroll
        for (int i = 0; i < 2; i++) {
            int idx = t + i * 256;
            int o   = idx >> 3;
            int kq  = idx & 7;
            float4 v = *(const float4*)&W[o * IN_FT + kt + kq * 4];
            sB[(kq * 4 + 0) * 64 + o] = v.x;
            sB[(kq * 4 + 1) * 64 + o] = v.y;
            sB[(kq * 4 + 2) * 64 + o] = v.z;
            sB[(kq * 4 + 3) * 64 + o] = v.w;
        }
        __syncthreads();

#pragma unroll
        for (int kk = 0; kk < 32; kk++) {
            float4 b = *(const float4*)&sB[kk * 64 + tx * 4];
            float a0 = sA[(ty * 4 + 0) * 32 + kk];
            float a1 = sA[(ty * 4 + 1) * 32 + kk];
            float a2 = sA[(ty * 4 + 2) * 32 + kk];
            float a3 = sA[(ty * 4 + 3) * 32 + kk];
            acc[0][0] += a0 * b.x; acc[0][1] += a0 * b.y; acc[0][2] += a0 * b.z; acc[0][3] += a0 * b.w;
            acc[1][0] += a1 * b.x; acc[1][1] += a1 * b.y; acc[1][2] += a1 * b.z; acc[1][3] += a1 * b.w;
            acc[2][0] += a2 * b.x; acc[2][1] += a2 * b.y; acc[2][2] += a2 * b.z; acc[2][3] += a2 * b.w;
            acc[3][0] += a3 * b.x; acc[3][1] += a3 * b.y; acc[3][2] += a3 * b.z; acc[3][3] += a3 * b.w;
        }
        __syncthreads();
    }

#pragma unroll
    for (int r = 0; r < 4; r++) {
        int row = row0 + ty * 4 + r;
        if (row < NN) {
            float4 v = make_float4(acc[r][0], acc[r][1], acc[r][2], acc[r][3]);
            *(float4*)&fts[(size_t)row * OUT_FT + tx * 4] = v;
        }
    }
}

// ---------------------------------------------------------------------------
// Init output to bias (bias is zeros in this problem, but honor the input).
// ---------------------------------------------------------------------------
__global__ void init_kernel(float* __restrict__ out, const float* __restrict__ bias)
{
    int i = blockIdx.x * blockDim.x + threadIdx.x;
    if (i < NN * OUT_FT) out[i] = bias[i & (OUT_FT - 1)];
}

// ---------------------------------------------------------------------------
// Scatter: for each edge e: out[dst] += fts[src] * val. 16 threads per edge,
// each handles a float4 chunk; vectorized RED (no return) to L2.
// ---------------------------------------------------------------------------
__global__ __launch_bounds__(256) void scatter_kernel(
    const float* __restrict__ fts,
    const int* __restrict__ esrc, const int* __restrict__ edst,
    const float* __restrict__ eval, float* __restrict__ out)
{
    long long gid = (long long)blockIdx.x * blockDim.x + threadIdx.x;
    int e    = (int)(gid >> 4);
    int part = (int)(gid & 15);
    if (e >= NE) return;

    int   s = __ldg(&esrc[e]);
    int   d = __ldg(&edst[e]);
    float v = __ldg(&eval[e]);

    float4 f = *(const float4*)&fts[(size_t)s * OUT_FT + part * 4];
    float* p = &out[(size_t)d * OUT_FT + part * 4];
    asm volatile("red.global.add.v4.f32 [%0], {%1, %2, %3, %4};"
                 :: "l"(p), "f"(f.x * v), "f"(f.y * v), "f"(f.z * v), "f"(f.w * v)
                 : "memory");
}

// ---------------------------------------------------------------------------
// PReLU (scalar alpha), in place.
// ---------------------------------------------------------------------------
__global__ void prelu_kernel(float* __restrict__ out, const float* __restrict__ alpha)
{
    int i = blockIdx.x * blockDim.x + threadIdx.x;
    if (i < NN * OUT_FT) {
        float a = __ldg(&alpha[0]);
        float x = out[i];
        out[i] = (x >= 0.0f) ? x : a * x;
    }
}

extern "C" void kernel_launch(void* const* d_in, const int* in_sizes, int n_in,
                              void* d_out, int out_size)
{
    const float* seq   = (const float*)d_in[0];
    const float* W     = (const float*)d_in[1];
    const float* bias  = (const float*)d_in[2];
    const float* alpha = (const float*)d_in[3];
    const int*   esrc  = (const int*)d_in[4];
    const int*   edst  = (const int*)d_in[5];
    const float* eval  = (const float*)d_in[6];
    float* out = (float*)d_out;

    float* fts;
    cudaGetSymbolAddress((void**)&fts, g_fts);

    // 1) GEMM: fts = seq @ W^T
    gemm_kernel<<<(NN + 63) / 64, 256>>>(seq, W, fts);

    // 2) out = bias (broadcast) — also un-poisons d_out
    init_kernel<<<(NN * OUT_FT + 255) / 256, 256>>>(out, bias);

    // 3) scatter-add over edges
    long long total = (long long)NE * 16;
    scatter_kernel<<<(unsigned)((total + 255) / 256), 256>>>(fts, esrc, edst, eval, out);

    // 4) PReLU in place
    prelu_kernel<<<(NN * OUT_FT + 255) / 256, 256>>>(out, alpha);
}